// round 10
// baseline (speedup 1.0000x reference)
#include <cuda_runtime.h>
#include <math.h>

// ---------------- problem constants ----------------
#define BATCH 4
#define DIM   1024
#define NHEAD 4
#define HD    256
#define FF    4096
#define MASKN 2304           // 48*48
#define NPM   2304           // max prompts
#define NMAX  3329           // 1024 + 1 + 2304
#define SLD   3332           // padded score leading dim (mult of 4)

// ---------------- static device scratch (no allocs allowed) ----------------
__device__ int   g_np[BATCH];
__device__ int   g_pidx[BATCH * NPM];
__device__ float g_qpe[1024 * DIM];
__device__ float g_ph[(size_t)BATCH * NPM * 512];
__device__ float g_prompt[(size_t)BATCH * NPM * DIM];
__device__ float g_x[(size_t)BATCH * NMAX * DIM];
__device__ float g_xn[(size_t)BATCH * NMAX * DIM];
__device__ float g_qkv[(size_t)BATCH * NMAX * 3 * DIM];
__device__ float g_ao[(size_t)BATCH * NMAX * DIM];
__device__ float g_hb[(size_t)BATCH * NMAX * FF];
__device__ float g_s[(size_t)BATCH * NHEAD * NMAX * SLD];

__device__ __forceinline__ float gelu_f(float v) {
    return 0.5f * v * (1.0f + erff(v * 0.7071067811865476f));
}

// bf16x2 2-term split: pack (x0 -> low half, x1 -> high half) hi pair + lo pair.
__device__ __forceinline__ void splitb(float x0, float x1, unsigned& h, unsigned& l) {
    unsigned hh;
    asm("cvt.rn.bf16x2.f32 %0, %1, %2;" : "=r"(hh) : "f"(x1), "f"(x0));
    float hf0 = __uint_as_float(hh << 16);
    float hf1 = __uint_as_float(hh & 0xFFFF0000u);
    float l0 = x0 - hf0;
    float l1 = x1 - hf1;
    unsigned ll;
    asm("cvt.rn.bf16x2.f32 %0, %1, %2;" : "=r"(ll) : "f"(l1), "f"(l0));
    h = hh; l = ll;
}

__device__ __forceinline__ void mma16(float* c, const unsigned* a, const unsigned* b) {
    asm volatile(
        "mma.sync.aligned.m16n8k16.row.col.f32.bf16.bf16.f32 "
        "{%0,%1,%2,%3}, {%4,%5,%6,%7}, {%8,%9}, {%0,%1,%2,%3};"
        : "+f"(c[0]), "+f"(c[1]), "+f"(c[2]), "+f"(c[3])
        : "r"(a[0]), "r"(a[1]), "r"(a[2]), "r"(a[3]), "r"(b[0]), "r"(b[1]));
}

__device__ __forceinline__ void ldsm4(unsigned& r0, unsigned& r1, unsigned& r2, unsigned& r3,
                                      unsigned addr) {
    asm volatile("ldmatrix.sync.aligned.m8n8.x4.shared.b16 {%0,%1,%2,%3}, [%4];"
                 : "=r"(r0), "=r"(r1), "=r"(r2), "=r"(r3) : "r"(addr));
}

// ---------------- mask compaction (row-major order preserved) ----------------
__global__ void k_scan(const int* __restrict__ mask) {
    int b = blockIdx.x, tid = threadIdx.x;
    const int PER = MASKN / 256;   // 9
    int base = b * MASKN;
    int flags[PER];
    int cnt = 0;
#pragma unroll
    for (int q = 0; q < PER; q++) {
        int i = tid * PER + q;
        int f = (mask[base + i] > 0) ? 1 : 0;
        flags[q] = f; cnt += f;
    }
    __shared__ int s[256];
    s[tid] = cnt; __syncthreads();
    for (int off = 1; off < 256; off <<= 1) {
        int v = (tid >= off) ? s[tid - off] : 0;
        __syncthreads();
        s[tid] += v;
        __syncthreads();
    }
    int excl = s[tid] - cnt;
#pragma unroll
    for (int q = 0; q < PER; q++)
        if (flags[q]) g_pidx[b * NPM + (excl++)] = tid * PER + q;
    if (tid == 255) g_np[b] = s[255];
}

// ---------------- query positional encoding (32x32 grid) ----------------
__global__ void k_qpe(const float* __restrict__ gauss) {
    int p = blockIdx.x, k = threadIdx.x;      // 1024 blocks x 512 threads
    int i = p >> 5, j = p & 31;
    float cx = 2.0f * ((j + 0.5f) / 32.0f) - 1.0f;
    float cy = 2.0f * ((i + 0.5f) / 32.0f) - 1.0f;
    float e = 6.283185307179586f * (cx * gauss[k] + cy * gauss[512 + k]);
    g_qpe[(size_t)p * DIM + k]       = sinf(e);
    g_qpe[(size_t)p * DIM + k + 512] = cosf(e);
}

// ---------------- prompt: depth->hidden gelu, and prompt PE ----------------
__global__ void k_prompt_init(const float* __restrict__ depth,
                              const float* __restrict__ gauss,
                              const float* __restrict__ w1,
                              const float* __restrict__ b1) {
    int j = blockIdx.x, b = blockIdx.y;
    if (j >= g_np[b]) return;
    int idx = g_pidx[b * NPM + j];
    int r = idx / 48, c = idx % 48;
    float d = depth[b * MASKN + idx];
    int tid = threadIdx.x;
    float* ph = &g_ph[((size_t)b * NPM + j) * 512];
    for (int k = tid; k < 512; k += 256)
        ph[k] = gelu_f(fmaf(d, w1[k], b1[k]));
    float cx = 2.0f * ((c + 0.5f) / 48.0f) - 1.0f;
    float cy = 2.0f * ((r + 0.5f) / 48.0f) - 1.0f;
    float* pr = &g_prompt[((size_t)b * NPM + j) * DIM];
    for (int k = tid; k < 512; k += 256) {
        float e = 6.283185307179586f * (cx * gauss[k] + cy * gauss[512 + k]);
        pr[k] = sinf(e);
        pr[k + 512] = cosf(e);
    }
}

// ---------------- build initial token stream x0 ----------------
__global__ void k_build(const float* __restrict__ img, const float* __restrict__ sep0) {
    int t = blockIdx.x, b = blockIdx.y;
    int np = g_np[b];
    if (t >= 1025 + np) return;
    float* x = &g_x[((size_t)b * NMAX + t) * DIM];
    int tid = threadIdx.x;
    if (t < 1024) {
        const float* im = &img[((size_t)b * 1024 + t) * DIM];
        const float* pe = &g_qpe[(size_t)t * DIM];
        for (int c = tid; c < DIM; c += 256) x[c] = im[c] + pe[c];
    } else if (t == 1024) {
        for (int c = tid; c < DIM; c += 256) x[c] = sep0[c];
    } else {
        const float* pr = &g_prompt[((size_t)b * NPM + (t - 1025)) * DIM];
        for (int c = tid; c < DIM; c += 256) x[c] = pr[c];
    }
}

__global__ void k_set_sep(const float* __restrict__ sepi) {
    int b = blockIdx.y, tid = threadIdx.x;
    float* x = &g_x[((size_t)b * NMAX + 1024) * DIM];
    for (int c = tid; c < DIM; c += 256) x[c] = sepi[c];
}

// ---------------- LayerNorm ----------------
__global__ void k_ln(const float* __restrict__ X, float* __restrict__ Y,
                     const float* __restrict__ w, const float* __restrict__ bb) {
    int t = blockIdx.x, b = blockIdx.y;
    if (t >= 1025 + g_np[b]) return;
    const float* x = X + ((size_t)b * NMAX + t) * DIM;
    float* y = Y + ((size_t)b * NMAX + t) * DIM;
    int tid = threadIdx.x;
    float v[4], s = 0.0f;
#pragma unroll
    for (int q = 0; q < 4; q++) { v[q] = x[tid + q * 256]; s += v[q]; }
    __shared__ float red[256];
    red[tid] = s; __syncthreads();
    for (int o = 128; o > 0; o >>= 1) {
        if (tid < o) red[tid] += red[tid + o];
        __syncthreads();
    }
    float mean = red[0] * (1.0f / DIM);
    __syncthreads();
    float s2 = 0.0f;
#pragma unroll
    for (int q = 0; q < 4; q++) { float d = v[q] - mean; s2 += d * d; }
    red[tid] = s2; __syncthreads();
    for (int o = 128; o > 0; o >>= 1) {
        if (tid < o) red[tid] += red[tid + o];
        __syncthreads();
    }
    float rstd = rsqrtf(red[0] * (1.0f / DIM) + 1e-5f);
#pragma unroll
    for (int q = 0; q < 4; q++) {
        int c = tid + q * 256;
        y[c] = (v[q] - mean) * rstd * w[c] + bb[c];
    }
}

// =============================================================================
// BF16 split MMA GEMM, row-major packed smem + LDSM fragments, KT=32,
// double-buffered. 128x128 CTA tile, 8 warps (2x4), warp tile 64x32.
// Smem tile layout: [row][k2] (k contiguous), row stride RS=20 words
// (conflict-free ldmatrix phases + 16B-aligned STS.128 staging).
// 3-term split: hi*hi + hi*lo + lo*hi.
// =============================================================================
#define KT   32
#define RS   20                           // words per row (16 data + 4 pad)
#define ARRW (128 * RS)                   // words per array (2560)
#define STGW (4 * ARRW)                   // words per stage (Ah,Al,Bh,Bl)
#define SMEM_BYTES (2 * STGW * 4)         // 81920 B

// ---- per-tile mma with ldmatrix fragment loads (operates on one buffer) ----
__device__ __forceinline__ void mma_tile(
    float acc[4][4][4], unsigned sb /* shared byte addr of buffer */,
    int wm, int wn, int lane)
{
    int rowa = wm * 64 + (lane & 15);
    int cha  = (lane >> 4) & 1;
    int rowb = wn * 32 + (lane & 7) + ((lane >> 4) & 1) * 8;
    int chb  = (lane >> 3) & 1;
    unsigned aA = sb + (unsigned)(rowa * RS + cha * 4) * 4u;
    unsigned aB = sb + 2u * ARRW * 4u + (unsigned)(rowb * RS + chb * 4) * 4u;
    const unsigned LOFF = ARRW * 4u;       // hi->lo array offset
    const unsigned G16  = 16u * RS * 4u;   // 16-row group stride
#pragma unroll
    for (int ks = 0; ks < 2; ks++) {
        unsigned kw = (unsigned)(ks * 8) * 4u;
        unsigned bh[4][2], bl[4][2], ah[4][4], al[4][4];
        ldsm4(bh[0][0], bh[0][1], bh[1][0], bh[1][1], aB + kw);
        ldsm4(bh[2][0], bh[2][1], bh[3][0], bh[3][1], aB + G16 + kw);
        ldsm4(bl[0][0], bl[0][1], bl[1][0], bl[1][1], aB + LOFF + kw);
        ldsm4(bl[2][0], bl[2][1], bl[3][0], bl[3][1], aB + LOFF + G16 + kw);
#pragma unroll
        for (int ma = 0; ma < 4; ma++) {
            ldsm4(ah[ma][0], ah[ma][1], ah[ma][2], ah[ma][3], aA + ma * G16 + kw);
            ldsm4(al[ma][0], al[ma][1], al[ma][2], al[ma][3], aA + LOFF + ma * G16 + kw);
        }
#pragma unroll
        for (int mp = 0; mp < 2; mp++) {
            int ma0 = mp * 2, ma1 = mp * 2 + 1;
#pragma unroll
            for (int na = 0; na < 4; na++) mma16(acc[ma0][na], ah[ma0], bh[na]);
#pragma unroll
            for (int na = 0; na < 4; na++) mma16(acc[ma1][na], ah[ma1], bh[na]);
#pragma unroll
            for (int na = 0; na < 4; na++) mma16(acc[ma0][na], ah[ma0], bl[na]);
#pragma unroll
            for (int na = 0; na < 4; na++) mma16(acc[ma1][na], ah[ma1], bl[na]);
#pragma unroll
            for (int na = 0; na < 4; na++) mma16(acc[ma0][na], al[ma0], bh[na]);
#pragma unroll
            for (int na = 0; na < 4; na++) mma16(acc[ma1][na], al[ma1], bh[na]);
        }
    }
}

// stage one KT=32 tile (NN) into buffer at 'base' (generic ptr)
__device__ __forceinline__ void stage_nn(
    unsigned* base,
    const float* __restrict__ A, long long lda, int M, int K, int m0,
    const float* __restrict__ Bw, long long ldb, int n0,
    int k0, int tid)
{
    unsigned* Ah = base;
    unsigned* Al = base + ARRW;
    unsigned* Bh = base + 2 * ARRW;
    unsigned* Bl = base + 3 * ARRW;
    int ar = tid >> 1, ak2 = (tid & 1) * 8;
    // A: row m0+ar, 16 k-values -> 8 packed words at [ar][ak2..ak2+7]
    {
        int gm = m0 + ar;
        bool mok = gm < M;
        const float* ap = A + (long long)gm * lda + k0 + ak2 * 2;
        float av[16];
#pragma unroll
        for (int q = 0; q < 4; q++) {
            float4 v = make_float4(0.f, 0.f, 0.f, 0.f);
            int gk = k0 + ak2 * 2 + q * 4;
            if (mok) {
                if (gk + 3 < K) v = *(const float4*)(ap + q * 4);
                else {
                    if (gk + 0 < K) v.x = ap[q * 4 + 0];
                    if (gk + 1 < K) v.y = ap[q * 4 + 1];
                    if (gk + 2 < K) v.z = ap[q * 4 + 2];
                    if (gk + 3 < K) v.w = ap[q * 4 + 3];
                }
            }
            av[q * 4 + 0] = v.x; av[q * 4 + 1] = v.y;
            av[q * 4 + 2] = v.z; av[q * 4 + 3] = v.w;
        }
        uint4 h0, l0, h1, l1;
        splitb(av[0],  av[1],  h0.x, l0.x);
        splitb(av[2],  av[3],  h0.y, l0.y);
        splitb(av[4],  av[5],  h0.z, l0.z);
        splitb(av[6],  av[7],  h0.w, l0.w);
        splitb(av[8],  av[9],  h1.x, l1.x);
        splitb(av[10], av[11], h1.y, l1.y);
        splitb(av[12], av[13], h1.z, l1.z);
        splitb(av[14], av[15], h1.w, l1.w);
        *(uint4*)(Ah + ar * RS + ak2)     = h0;
        *(uint4*)(Ah + ar * RS + ak2 + 4) = h1;
        *(uint4*)(Al + ar * RS + ak2)     = l0;
        *(uint4*)(Al + ar * RS + ak2 + 4) = l1;
    }
    // B: 4 k-rows x 4 n-cols -> per n, uint2 {pair0,pair1} at [bn+j][bk2..bk2+1]
    {
        int bk0 = (tid >> 5) * 4, bn = (tid & 31) * 4, bk2 = (tid >> 5) * 2;
        float bvv[4][4];
#pragma unroll
        for (int i = 0; i < 4; i++) {
            int gk = k0 + bk0 + i;
            float4 v = make_float4(0.f, 0.f, 0.f, 0.f);
            if (gk < K) v = *(const float4*)(Bw + (long long)gk * ldb + n0 + bn);
            bvv[i][0] = v.x; bvv[i][1] = v.y; bvv[i][2] = v.z; bvv[i][3] = v.w;
        }
#pragma unroll
        for (int j = 0; j < 4; j++) {
            unsigned h0, l0, h1, l1;
            splitb(bvv[0][j], bvv[1][j], h0, l0);
            splitb(bvv[2][j], bvv[3][j], h1, l1);
            uint2 hv; hv.x = h0; hv.y = h1;
            uint2 lv; lv.x = l0; lv.y = l1;
            *(uint2*)(Bh + (bn + j) * RS + bk2) = hv;
            *(uint2*)(Bl + (bn + j) * RS + bk2) = lv;
        }
    }
}

// stage one tile for NT (both operands row-major k-contiguous)
__device__ __forceinline__ void stage_nt(
    unsigned* base,
    const float* __restrict__ arow, bool mok,
    const float* __restrict__ brow, bool nok,
    int k0, int ar, int ak2)
{
    unsigned* Ah = base;
    unsigned* Al = base + ARRW;
    unsigned* Bh = base + 2 * ARRW;
    unsigned* Bl = base + 3 * ARRW;
    float av[16], bv[16];
#pragma unroll
    for (int q = 0; q < 4; q++) {
        float4 v = make_float4(0.f, 0.f, 0.f, 0.f);
        if (mok) v = *(const float4*)(arow + k0 + ak2 * 2 + q * 4);
        av[q * 4 + 0] = v.x; av[q * 4 + 1] = v.y;
        av[q * 4 + 2] = v.z; av[q * 4 + 3] = v.w;
        float4 w = make_float4(0.f, 0.f, 0.f, 0.f);
        if (nok) w = *(const float4*)(brow + k0 + ak2 * 2 + q * 4);
        bv[q * 4 + 0] = w.x; bv[q * 4 + 1] = w.y;
        bv[q * 4 + 2] = w.z; bv[q * 4 + 3] = w.w;
    }
    uint4 h0, l0, h1, l1;
    splitb(av[0],  av[1],  h0.x, l0.x);
    splitb(av[2],  av[3],  h0.y, l0.y);
    splitb(av[4],  av[5],  h0.z, l0.z);
    splitb(av[6],  av[7],  h0.w, l0.w);
    splitb(av[8],  av[9],  h1.x, l1.x);
    splitb(av[10], av[11], h1.y, l1.y);
    splitb(av[12], av[13], h1.z, l1.z);
    splitb(av[14], av[15], h1.w, l1.w);
    *(uint4*)(Ah + ar * RS + ak2)     = h0;
    *(uint4*)(Ah + ar * RS + ak2 + 4) = h1;
    *(uint4*)(Al + ar * RS + ak2)     = l0;
    *(uint4*)(Al + ar * RS + ak2 + 4) = l1;
    splitb(bv[0],  bv[1],  h0.x, l0.x);
    splitb(bv[2],  bv[3],  h0.y, l0.y);
    splitb(bv[4],  bv[5],  h0.z, l0.z);
    splitb(bv[6],  bv[7],  h0.w, l0.w);
    splitb(bv[8],  bv[9],  h1.x, l1.x);
    splitb(bv[10], bv[11], h1.y, l1.y);
    splitb(bv[12], bv[13], h1.z, l1.z);
    splitb(bv[14], bv[15], h1.w, l1.w);
    *(uint4*)(Bh + ar * RS + ak2)     = h0;
    *(uint4*)(Bh + ar * RS + ak2 + 4) = h1;
    *(uint4*)(Bl + ar * RS + ak2)     = l0;
    *(uint4*)(Bl + ar * RS + ak2 + 4) = l1;
}

// EPI: 0 = store, 1 = gelu-store, 2 = add-to-C (residual)
template<int EPI>
__global__ void __launch_bounds__(256, 2)
k_mma_nn(const float* __restrict__ A, long long lda, long long sAb, long long sAh,
         const float* __restrict__ Bw, long long ldb, long long sBb, long long sBh,
         const float* __restrict__ bias,
         float* __restrict__ C, long long ldc, long long sCb, long long sCh,
         int zdiv, int m_base, int Kfix, float scale) {
    int z = blockIdx.z, b = z / zdiv, h = z - b * zdiv;
    int M = m_base + g_np[b];
    int m0 = blockIdx.y * 128;
    if (m0 >= M) return;
    int K = (Kfix > 0) ? Kfix : M;
    int n0 = blockIdx.x * 128;
    A  += (long long)b * sAb + (long long)h * sAh;
    Bw += (long long)b * sBb + (long long)h * sBh;
    C  += (long long)b * sCb + (long long)h * sCh;
    extern __shared__ unsigned smem_u[];
    unsigned sbase = (unsigned)__cvta_generic_to_shared(smem_u);
    int tid = threadIdx.x, lane = tid & 31, warp = tid >> 5;
    int g = lane >> 2, t = lane & 3;
    int wm = warp & 1, wn = warp >> 1;
    float acc[4][4][4] = {};

    stage_nn(smem_u, A, lda, M, K, m0, Bw, ldb, n0, 0, tid);
    __syncthreads();
    int buf = 0;
    for (int k0 = 0; k0 < K; k0 += KT) {
        int kn = k0 + KT;
        if (kn < K) stage_nn(smem_u + (buf ^ 1) * STGW, A, lda, M, K, m0, Bw, ldb, n0, kn, tid);
        mma_tile(acc, sbase + (unsigned)buf * STGW * 4u, wm, wn, lane);
        __syncthreads();
        buf ^= 1;
    }
    // ---- epilogue ----
#pragma unroll
    for (int ma = 0; ma < 4; ma++) {
        int r0 = m0 + wm * 64 + ma * 16 + g;
#pragma unroll
        for (int half = 0; half < 2; half++) {
            int gm = r0 + half * 8;
            if (gm >= M) continue;
            float* crow = C + (long long)gm * ldc;
#pragma unroll
            for (int na = 0; na < 4; na++) {
                int gn = n0 + wn * 32 + na * 8 + t * 2;
                float v0 = acc[ma][na][half * 2 + 0] * scale + (bias ? bias[gn] : 0.0f);
                float v1 = acc[ma][na][half * 2 + 1] * scale + (bias ? bias[gn + 1] : 0.0f);
                if (EPI == 1) { v0 = gelu_f(v0); v1 = gelu_f(v1); }
                if (EPI == 2) { crow[gn] += v0; crow[gn + 1] += v1; }
                else          { crow[gn] = v0;  crow[gn + 1] = v1; }
            }
        }
    }
}

// =============================================================================
// NT variant: attention scores C[nq][nk] = scale * Q @ K^T, K = HD = 256.
// =============================================================================
__global__ void __launch_bounds__(256, 2)
k_mma_nt(const float* __restrict__ A, long long lda, long long sAb, long long sAh,
         const float* __restrict__ Bk, long long ldb, long long sBb, long long sBh,
         float* __restrict__ C, long long ldc, long long sCb, long long sCh,
         float scale) {
    int z = blockIdx.z, b = z >> 2, h = z & 3;
    int M = 1025 + g_np[b];
    int m0 = blockIdx.y * 128;
    int n0 = blockIdx.x * 128;
    if (m0 >= M || n0 >= M) return;
    A  += (long long)b * sAb + (long long)h * sAh;
    Bk += (long long)b * sBb + (long long)h * sBh;
    C  += (long long)b * sCb + (long long)h * sCh;
    extern __shared__ unsigned smem_u[];
    unsigned sbase = (unsigned)__cvta_generic_to_shared(smem_u);
    int tid = threadIdx.x, lane = tid & 31, warp = tid >> 5;
    int g = lane >> 2, t = lane & 3;
    int wm = warp & 1, wn = warp >> 1;
    float acc[4][4][4] = {};
    int ar = tid >> 1, ak2 = (tid & 1) * 8;
    int gm = m0 + ar, gn = n0 + ar;
    bool mok = gm < M, nok = gn < M;
    const float* arow = A + (long long)gm * lda;
    const float* brow = Bk + (long long)gn * ldb;

    stage_nt(smem_u, arow, mok, brow, nok, 0, ar, ak2);
    __syncthreads();
    int buf = 0;
    for (int k0 = 0; k0 < HD; k0 += KT) {
        int kn = k0 + KT;
        if (kn < HD) stage_nt(smem_u + (buf ^ 1) * STGW, arow, mok, brow, nok, kn, ar, ak2);
        mma_tile(acc, sbase + (unsigned)buf * STGW * 4u, wm, wn, lane);
        __syncthreads();
        buf ^= 1;
    }
#pragma unroll
    for (int ma = 0; ma < 4; ma++) {
        int r0 = m0 + wm * 64 + ma * 16 + g;
#pragma unroll
        for (int half = 0; half < 2; half++) {
            int gmr = r0 + half * 8;
            if (gmr >= M) continue;
            float* crow = C + (long long)gmr * ldc;
#pragma unroll
            for (int na = 0; na < 4; na++) {
                int gnc = n0 + wn * 32 + na * 8 + t * 2;
                if (gnc >= M) continue;
                crow[gnc]     = acc[ma][na][half * 2 + 0] * scale;
                crow[gnc + 1] = acc[ma][na][half * 2 + 1] * scale;
            }
        }
    }
}

// ---------------- row softmax: online (max,sum) then single write pass ----
__global__ void k_softmax() {
    int n = blockIdx.x, h = blockIdx.y, b = blockIdx.z;
    int L = 1025 + g_np[b];
    if (n >= L) return;
    float* row = &g_s[((size_t)(b * NHEAD + h) * NMAX + n) * SLD];
    int tid = threadIdx.x;
    __shared__ float smx[256], ssm[256];
    float mx = -1e30f, sm = 0.0f;
    for (int m = tid; m < L; m += 256) {
        float v = row[m];
        float nm = fmaxf(mx, v);
        sm = sm * __expf(mx - nm) + __expf(v - nm);
        mx = nm;
    }
    smx[tid] = mx; ssm[tid] = sm;
    __syncthreads();
    for (int o = 128; o > 0; o >>= 1) {
        if (tid < o) {
            float m2 = smx[tid + o], s2 = ssm[tid + o];
            float m1 = smx[tid],     s1 = ssm[tid];
            float nm = fmaxf(m1, m2);
            ssm[tid] = s1 * __expf(m1 - nm) + s2 * __expf(m2 - nm);
            smx[tid] = nm;
        }
        __syncthreads();
    }
    float gmx = smx[0];
    float inv = 1.0f / ssm[0];
    for (int m = tid; m < L; m += 256)
        row[m] = __expf(row[m] - gmx) * inv;
}

// ---------------- final output ----------------
__global__ void k_out(const float* __restrict__ img, float* __restrict__ out) {
    int t = blockIdx.x, b = blockIdx.y, tid = threadIdx.x;
    bool use = (g_np[b] > 0);
    const float* x = &g_x[((size_t)b * NMAX + t) * DIM];
    const float* im = &img[((size_t)b * 1024 + t) * DIM];
    float* o = &out[((size_t)b * 1024 + t) * DIM];
    for (int c = tid; c < DIM; c += 256) o[c] = use ? x[c] : im[c];
}

// ---------------- launcher ----------------
extern "C" void kernel_launch(void* const* d_in, const int* in_sizes, int n_in,
                              void* d_out, int out_size) {
    const float* img   = (const float*)d_in[0];
    const float* depth = (const float*)d_in[1];
    const int*   mask  = (const int*)d_in[2];
    const float* gauss = (const float*)d_in[5];
    const float* w1    = (const float*)d_in[6];
    const float* b1    = (const float*)d_in[7];
    const float* w2    = (const float*)d_in[8];
    const float* b2    = (const float*)d_in[9];
    const float* sep   = (const float*)d_in[10];
    const float* ln1w  = (const float*)d_in[11];
    const float* ln1b  = (const float*)d_in[12];
    const float* qkvw  = (const float*)d_in[13];
    const float* qkvb  = (const float*)d_in[14];
    const float* projw = (const float*)d_in[15];
    const float* projb = (const float*)d_in[16];
    const float* ln2w  = (const float*)d_in[17];
    const float* ln2b  = (const float*)d_in[18];
    const float* m1w   = (const float*)d_in[19];
    const float* m1b   = (const float*)d_in[20];
    const float* m2w   = (const float*)d_in[21];
    const float* m2b   = (const float*)d_in[22];
    float* out = (float*)d_out;

    float *p_ph, *p_prompt, *p_x, *p_xn, *p_qkv, *p_ao, *p_hb, *p_s;
    cudaGetSymbolAddress((void**)&p_ph, g_ph);
    cudaGetSymbolAddress((void**)&p_prompt, g_prompt);
    cudaGetSymbolAddress((void**)&p_x, g_x);
    cudaGetSymbolAddress((void**)&p_xn, g_xn);
    cudaGetSymbolAddress((void**)&p_qkv, g_qkv);
    cudaGetSymbolAddress((void**)&p_ao, g_ao);
    cudaGetSymbolAddress((void**)&p_hb, g_hb);
    cudaGetSymbolAddress((void**)&p_s, g_s);

    cudaFuncSetAttribute(k_mma_nn<0>, cudaFuncAttributeMaxDynamicSharedMemorySize, SMEM_BYTES);
    cudaFuncSetAttribute(k_mma_nn<1>, cudaFuncAttributeMaxDynamicSharedMemorySize, SMEM_BYTES);
    cudaFuncSetAttribute(k_mma_nn<2>, cudaFuncAttributeMaxDynamicSharedMemorySize, SMEM_BYTES);
    cudaFuncSetAttribute(k_mma_nt,    cudaFuncAttributeMaxDynamicSharedMemorySize, SMEM_BYTES);

    k_scan<<<BATCH, 256>>>(mask);
    k_qpe<<<1024, 512>>>(gauss);
    k_prompt_init<<<dim3(NPM, BATCH), 256>>>(depth, gauss, w1, b1);
    // prompt = ph @ w2 + b2, added onto PE already stored in g_prompt
    k_mma_nn<2><<<dim3(8, 18, BATCH), 256, SMEM_BYTES>>>(
        p_ph, 512, (long long)NPM * 512, 0,
        w2, 1024, 0, 0, b2,
        p_prompt, 1024, (long long)NPM * 1024, 0,
        1, 0, 512, 1.0f);
    k_build<<<dim3(NMAX, BATCH), 256>>>(img, sep);

    for (int i = 0; i < 2; i++) {
        if (i) k_set_sep<<<dim3(1, BATCH), 256>>>(sep + (size_t)i * DIM);
        // ln1
        k_ln<<<dim3(NMAX, BATCH), 256>>>(p_x, p_xn, ln1w + i * DIM, ln1b + i * DIM);
        // qkv
        k_mma_nn<0><<<dim3(24, 27, BATCH), 256, SMEM_BYTES>>>(
            p_xn, DIM, (long long)NMAX * DIM, 0,
            qkvw + (size_t)i * DIM * 3 * DIM, 3 * DIM, 0, 0, qkvb + (size_t)i * 3 * DIM,
            p_qkv, 3 * DIM, (long long)NMAX * 3 * DIM, 0,
            1, 1025, DIM, 1.0f);
        // scores = (q @ k^T) / 16
        k_mma_nt<<<dim3(27, 27, BATCH * NHEAD), 256, SMEM_BYTES>>>(
            p_qkv, 3 * DIM, (long long)NMAX * 3 * DIM, HD,
            p_qkv + DIM, 3 * DIM, (long long)NMAX * 3 * DIM, HD,
            p_s, SLD, (long long)NHEAD * NMAX * SLD, (long long)NMAX * SLD,
            0.0625f);
        k_softmax<<<dim3(NMAX, NHEAD, BATCH), 256>>>();
        // attn out = softmax @ v
        k_mma_nn<0><<<dim3(2, 27, BATCH * NHEAD), 256, SMEM_BYTES>>>(
            p_s, SLD, (long long)NHEAD * NMAX * SLD, (long long)NMAX * SLD,
            p_qkv + 2 * DIM, 3 * DIM, (long long)NMAX * 3 * DIM, HD, nullptr,
            p_ao, DIM, (long long)NMAX * DIM, HD,
            NHEAD, 1025, -1, 1.0f);
        // proj + residual
        k_mma_nn<2><<<dim3(8, 27, BATCH), 256, SMEM_BYTES>>>(
            p_ao, DIM, (long long)NMAX * DIM, 0,
            projw + (size_t)i * DIM * DIM, DIM, 0, 0, projb + (size_t)i * DIM,
            p_x, DIM, (long long)NMAX * DIM, 0,
            1, 1025, DIM, 1.0f);
        // ln2
        k_ln<<<dim3(NMAX, BATCH), 256>>>(p_x, p_xn, ln2w + i * DIM, ln2b + i * DIM);
        // mlp1 (gelu)
        k_mma_nn<1><<<dim3(32, 27, BATCH), 256, SMEM_BYTES>>>(
            p_xn, DIM, (long long)NMAX * DIM, 0,
            m1w + (size_t)i * DIM * FF, FF, 0, 0, m1b + (size_t)i * FF,
            p_hb, FF, (long long)NMAX * FF, 0,
            1, 1025, DIM, 1.0f);
        // mlp2 + residual
        k_mma_nn<2><<<dim3(8, 27, BATCH), 256, SMEM_BYTES>>>(
            p_hb, FF, (long long)NMAX * FF, 0,
            m2w + (size_t)i * FF * DIM, DIM, 0, 0, m2b + (size_t)i * DIM,
            p_x, DIM, (long long)NMAX * DIM, 0,
            1, 1025, FF, 1.0f);
    }
    k_out<<<dim3(1024, BATCH), 256>>>(img, out);
}

// round 13
// speedup vs baseline: 1.1097x; 1.1097x over previous
#include <cuda_runtime.h>
#include <math.h>

// ---------------- problem constants ----------------
#define BATCH 4
#define DIM   1024
#define NHEAD 4
#define HD    256
#define FF    4096
#define MASKN 2304           // 48*48
#define NPM   2304           // max prompts
#define NMAX  3329           // 1024 + 1 + 2304
#define SLD   3332           // padded score leading dim (mult of 4)

// ---------------- static device scratch (no allocs allowed) ----------------
__device__ int   g_np[BATCH];
__device__ int   g_pidx[BATCH * NPM];
__device__ float g_qpe[1024 * DIM];
__device__ float g_ph[(size_t)BATCH * NPM * 512];
__device__ float g_prompt[(size_t)BATCH * NPM * DIM];
__device__ float g_x[(size_t)BATCH * NMAX * DIM];
__device__ float g_xn[(size_t)BATCH * NMAX * DIM];
__device__ float g_qkv[(size_t)BATCH * NMAX * 3 * DIM];
__device__ float g_ao[(size_t)BATCH * NMAX * DIM];
__device__ float g_hb[(size_t)BATCH * NMAX * FF];
__device__ float g_s[(size_t)BATCH * NHEAD * NMAX * SLD];
__device__ float g_mx[(size_t)BATCH * NHEAD * NMAX];
__device__ float g_inv[(size_t)BATCH * NHEAD * NMAX];

__device__ __forceinline__ float gelu_f(float v) {
    return 0.5f * v * (1.0f + erff(v * 0.7071067811865476f));
}

// bf16x2 2-term split: pack (x0 -> low half, x1 -> high half) hi pair + lo pair.
__device__ __forceinline__ void splitb(float x0, float x1, unsigned& h, unsigned& l) {
    unsigned hh;
    asm("cvt.rn.bf16x2.f32 %0, %1, %2;" : "=r"(hh) : "f"(x1), "f"(x0));
    float hf0 = __uint_as_float(hh << 16);
    float hf1 = __uint_as_float(hh & 0xFFFF0000u);
    float l0 = x0 - hf0;
    float l1 = x1 - hf1;
    unsigned ll;
    asm("cvt.rn.bf16x2.f32 %0, %1, %2;" : "=r"(ll) : "f"(l1), "f"(l0));
    h = hh; l = ll;
}

__device__ __forceinline__ void mma16(float* c, const unsigned* a, const unsigned* b) {
    asm volatile(
        "mma.sync.aligned.m16n8k16.row.col.f32.bf16.bf16.f32 "
        "{%0,%1,%2,%3}, {%4,%5,%6,%7}, {%8,%9}, {%0,%1,%2,%3};"
        : "+f"(c[0]), "+f"(c[1]), "+f"(c[2]), "+f"(c[3])
        : "r"(a[0]), "r"(a[1]), "r"(a[2]), "r"(a[3]), "r"(b[0]), "r"(b[1]));
}

// ---------------- mask compaction (row-major order preserved) ----------------
__global__ void k_scan(const int* __restrict__ mask) {
    int b = blockIdx.x, tid = threadIdx.x;
    const int PER = MASKN / 256;   // 9
    int base = b * MASKN;
    int flags[PER];
    int cnt = 0;
#pragma unroll
    for (int q = 0; q < PER; q++) {
        int i = tid * PER + q;
        int f = (mask[base + i] > 0) ? 1 : 0;
        flags[q] = f; cnt += f;
    }
    __shared__ int s[256];
    s[tid] = cnt; __syncthreads();
    for (int off = 1; off < 256; off <<= 1) {
        int v = (tid >= off) ? s[tid - off] : 0;
        __syncthreads();
        s[tid] += v;
        __syncthreads();
    }
    int excl = s[tid] - cnt;
#pragma unroll
    for (int q = 0; q < PER; q++)
        if (flags[q]) g_pidx[b * NPM + (excl++)] = tid * PER + q;
    if (tid == 255) g_np[b] = s[255];
}

// ---------------- query positional encoding (32x32 grid) ----------------
__global__ void k_qpe(const float* __restrict__ gauss) {
    int p = blockIdx.x, k = threadIdx.x;      // 1024 blocks x 512 threads
    int i = p >> 5, j = p & 31;
    float cx = 2.0f * ((j + 0.5f) / 32.0f) - 1.0f;
    float cy = 2.0f * ((i + 0.5f) / 32.0f) - 1.0f;
    float e = 6.283185307179586f * (cx * gauss[k] + cy * gauss[512 + k]);
    g_qpe[(size_t)p * DIM + k]       = sinf(e);
    g_qpe[(size_t)p * DIM + k + 512] = cosf(e);
}

// ---------------- prompt: depth->hidden gelu, and prompt PE ----------------
__global__ void k_prompt_init(const float* __restrict__ depth,
                              const float* __restrict__ gauss,
                              const float* __restrict__ w1,
                              const float* __restrict__ b1) {
    int j = blockIdx.x, b = blockIdx.y;
    if (j >= g_np[b]) return;
    int idx = g_pidx[b * NPM + j];
    int r = idx / 48, c = idx % 48;
    float d = depth[b * MASKN + idx];
    int tid = threadIdx.x;
    float* ph = &g_ph[((size_t)b * NPM + j) * 512];
    for (int k = tid; k < 512; k += 256)
        ph[k] = gelu_f(fmaf(d, w1[k], b1[k]));
    float cx = 2.0f * ((c + 0.5f) / 48.0f) - 1.0f;
    float cy = 2.0f * ((r + 0.5f) / 48.0f) - 1.0f;
    float* pr = &g_prompt[((size_t)b * NPM + j) * DIM];
    for (int k = tid; k < 512; k += 256) {
        float e = 6.283185307179586f * (cx * gauss[k] + cy * gauss[512 + k]);
        pr[k] = sinf(e);
        pr[k + 512] = cosf(e);
    }
}

// ---------------- build initial token stream x0 ----------------
__global__ void k_build(const float* __restrict__ img, const float* __restrict__ sep0) {
    int t = blockIdx.x, b = blockIdx.y;
    int np = g_np[b];
    if (t >= 1025 + np) return;
    float* x = &g_x[((size_t)b * NMAX + t) * DIM];
    int tid = threadIdx.x;
    if (t < 1024) {
        const float* im = &img[((size_t)b * 1024 + t) * DIM];
        const float* pe = &g_qpe[(size_t)t * DIM];
        for (int c = tid; c < DIM; c += 256) x[c] = im[c] + pe[c];
    } else if (t == 1024) {
        for (int c = tid; c < DIM; c += 256) x[c] = sep0[c];
    } else {
        const float* pr = &g_prompt[((size_t)b * NPM + (t - 1025)) * DIM];
        for (int c = tid; c < DIM; c += 256) x[c] = pr[c];
    }
}

__global__ void k_set_sep(const float* __restrict__ sepi) {
    int b = blockIdx.y, tid = threadIdx.x;
    float* x = &g_x[((size_t)b * NMAX + 1024) * DIM];
    for (int c = tid; c < DIM; c += 256) x[c] = sepi[c];
}

// ---------------- LayerNorm ----------------
__global__ void k_ln(const float* __restrict__ X, float* __restrict__ Y,
                     const float* __restrict__ w, const float* __restrict__ bb) {
    int t = blockIdx.x, b = blockIdx.y;
    if (t >= 1025 + g_np[b]) return;
    const float* x = X + ((size_t)b * NMAX + t) * DIM;
    float* y = Y + ((size_t)b * NMAX + t) * DIM;
    int tid = threadIdx.x;
    float v[4], s = 0.0f;
#pragma unroll
    for (int q = 0; q < 4; q++) { v[q] = x[tid + q * 256]; s += v[q]; }
    __shared__ float red[256];
    red[tid] = s; __syncthreads();
    for (int o = 128; o > 0; o >>= 1) {
        if (tid < o) red[tid] += red[tid + o];
        __syncthreads();
    }
    float mean = red[0] * (1.0f / DIM);
    __syncthreads();
    float s2 = 0.0f;
#pragma unroll
    for (int q = 0; q < 4; q++) { float d = v[q] - mean; s2 += d * d; }
    red[tid] = s2; __syncthreads();
    for (int o = 128; o > 0; o >>= 1) {
        if (tid < o) red[tid] += red[tid + o];
        __syncthreads();
    }
    float rstd = rsqrtf(red[0] * (1.0f / DIM) + 1e-5f);
#pragma unroll
    for (int q = 0; q < 4; q++) {
        int c = tid + q * 256;
        y[c] = (v[q] - mean) * rstd * w[c] + bb[c];
    }
}

// =============================================================================
// BF16 split MMA GEMM, packed bf16x2 smem, KT=32, DOUBLE-BUFFERED (1 sync/iter).
// 128x128 CTA tile, 8 warps (2x4), warp tile 64x32.
// 3-term split: hi*hi + hi*lo + lo*hi. Inner loop = pure LDS + HMMA.
// Optional fused softmax on A operand: a = exp(a - rowmax) * rowinv.
// =============================================================================
#define KT   32
#define KT2  16    // packed k rows
#define ALD  136   // 136 % 32 == 8 -> fragment LDS banks (8t+g), conflict-free
#define ARRW (KT2 * ALD)                  // words per smem array
#define STGW (4 * ARRW)                   // words per stage (Ah,Al,Bh,Bl)
#define SMEM_BYTES (2 * STGW * 4)         // 69632 B

typedef unsigned (*SArr)[ALD];

#define MMA_BODY(As_h, As_l, Bs_h, Bs_l)                                          \
    _Pragma("unroll")                                                             \
    for (int ks = 0; ks < 2; ks++) {                                              \
        int kb2 = ks * 8;                                                         \
        unsigned bh[4][2], bl[4][2];                                              \
        _Pragma("unroll")                                                         \
        for (int na = 0; na < 4; na++) {                                          \
            int c = wn * 32 + na * 8 + g;                                         \
            bh[na][0] = Bs_h[kb2 + t][c]; bh[na][1] = Bs_h[kb2 + t + 4][c];       \
            bl[na][0] = Bs_l[kb2 + t][c]; bl[na][1] = Bs_l[kb2 + t + 4][c];       \
        }                                                                         \
        _Pragma("unroll")                                                         \
        for (int mp = 0; mp < 2; mp++) {                                          \
            unsigned a0h[4], a0l[4], a1h[4], a1l[4];                              \
            int r0 = wm * 64 + mp * 32 + g;                                       \
            int r1 = r0 + 16;                                                     \
            a0h[0] = As_h[kb2 + t][r0];     a0h[1] = As_h[kb2 + t][r0 + 8];       \
            a0h[2] = As_h[kb2 + t + 4][r0]; a0h[3] = As_h[kb2 + t + 4][r0 + 8];   \
            a0l[0] = As_l[kb2 + t][r0];     a0l[1] = As_l[kb2 + t][r0 + 8];       \
            a0l[2] = As_l[kb2 + t + 4][r0]; a0l[3] = As_l[kb2 + t + 4][r0 + 8];   \
            a1h[0] = As_h[kb2 + t][r1];     a1h[1] = As_h[kb2 + t][r1 + 8];       \
            a1h[2] = As_h[kb2 + t + 4][r1]; a1h[3] = As_h[kb2 + t + 4][r1 + 8];   \
            a1l[0] = As_l[kb2 + t][r1];     a1l[1] = As_l[kb2 + t][r1 + 8];       \
            a1l[2] = As_l[kb2 + t + 4][r1]; a1l[3] = As_l[kb2 + t + 4][r1 + 8];   \
            int ma0 = mp * 2, ma1 = mp * 2 + 1;                                   \
            _Pragma("unroll")                                                     \
            for (int na = 0; na < 4; na++) mma16(acc[ma0][na], a0h, bh[na]);      \
            _Pragma("unroll")                                                     \
            for (int na = 0; na < 4; na++) mma16(acc[ma1][na], a1h, bh[na]);      \
            _Pragma("unroll")                                                     \
            for (int na = 0; na < 4; na++) mma16(acc[ma0][na], a0h, bl[na]);      \
            _Pragma("unroll")                                                     \
            for (int na = 0; na < 4; na++) mma16(acc[ma1][na], a1h, bl[na]);      \
            _Pragma("unroll")                                                     \
            for (int na = 0; na < 4; na++) mma16(acc[ma0][na], a0l, bh[na]);      \
            _Pragma("unroll")                                                     \
            for (int na = 0; na < 4; na++) mma16(acc[ma1][na], a1l, bh[na]);      \
        }                                                                         \
    }

// stage one KT=32 tile (NN layout) into the packed buffers at 'base'.
// If ex != 0, A values are transformed a = exp(a - rm) * ri (fused softmax).
__device__ __forceinline__ void stage_nn(
    unsigned* base,
    const float* __restrict__ A, long long lda, int M, int K, int m0,
    const float* __restrict__ Bw, long long ldb, int n0,
    int k0, int tid, int ex, float rm, float ri)
{
    SArr As_h = (SArr)(base);
    SArr As_l = (SArr)(base + ARRW);
    SArr Bs_h = (SArr)(base + 2 * ARRW);
    SArr Bs_l = (SArr)(base + 3 * ARRW);
    int ar = tid >> 1, ak2 = (tid & 1) * 8;
    int bk0 = (tid >> 5) * 4, bn = (tid & 31) * 4, bk2 = (tid >> 5) * 2;
    // A: row m0+ar, 16 k-values
    {
        int gm = m0 + ar;
        bool mok = gm < M;
        const float* ap = A + (long long)gm * lda + k0 + ak2 * 2;
        float av[16];
#pragma unroll
        for (int q = 0; q < 4; q++) {
            float4 v = make_float4(0.f, 0.f, 0.f, 0.f);
            int gk = k0 + ak2 * 2 + q * 4;
            if (mok) {
                if (gk + 3 < K) v = *(const float4*)(ap + q * 4);
                else {
                    if (gk + 0 < K) v.x = ap[q * 4 + 0];
                    if (gk + 1 < K) v.y = ap[q * 4 + 1];
                    if (gk + 2 < K) v.z = ap[q * 4 + 2];
                    if (gk + 3 < K) v.w = ap[q * 4 + 3];
                }
            }
            av[q * 4 + 0] = v.x; av[q * 4 + 1] = v.y;
            av[q * 4 + 2] = v.z; av[q * 4 + 3] = v.w;
        }
        if (ex) {
            // beyond-K lanes become exp(-rm)*ri != 0, but B rows beyond K are
            // zeroed below, so those products contribute 0 to the mma.
#pragma unroll
            for (int j = 0; j < 16; j++) av[j] = __expf(av[j] - rm) * ri;
        }
#pragma unroll
        for (int j = 0; j < 8; j++) {
            unsigned hh, ll;
            splitb(av[2 * j], av[2 * j + 1], hh, ll);
            As_h[ak2 + j][ar] = hh;
            As_l[ak2 + j][ar] = ll;
        }
    }
    // B: 4 k-rows x 4 cols
    {
        float bvv[4][4];
#pragma unroll
        for (int i = 0; i < 4; i++) {
            int gk = k0 + bk0 + i;
            float4 v = make_float4(0.f, 0.f, 0.f, 0.f);
            if (gk < K) v = *(const float4*)(Bw + (long long)gk * ldb + n0 + bn);
            bvv[i][0] = v.x; bvv[i][1] = v.y; bvv[i][2] = v.z; bvv[i][3] = v.w;
        }
        uint4 h0, l0, h1, l1;
        splitb(bvv[0][0], bvv[1][0], h0.x, l0.x);
        splitb(bvv[0][1], bvv[1][1], h0.y, l0.y);
        splitb(bvv[0][2], bvv[1][2], h0.z, l0.z);
        splitb(bvv[0][3], bvv[1][3], h0.w, l0.w);
        splitb(bvv[2][0], bvv[3][0], h1.x, l1.x);
        splitb(bvv[2][1], bvv[3][1], h1.y, l1.y);
        splitb(bvv[2][2], bvv[3][2], h1.z, l1.z);
        splitb(bvv[2][3], bvv[3][3], h1.w, l1.w);
        *(uint4*)&Bs_h[bk2][bn]     = h0;
        *(uint4*)&Bs_l[bk2][bn]     = l0;
        *(uint4*)&Bs_h[bk2 + 1][bn] = h1;
        *(uint4*)&Bs_l[bk2 + 1][bn] = l1;
    }
}

// stage one tile for NT (A rows + B rows, both k-contiguous)
__device__ __forceinline__ void stage_nt(
    unsigned* base,
    const float* __restrict__ arow, bool mok,
    const float* __restrict__ brow, bool nok,
    int k0, int ar, int ak2)
{
    SArr As_h = (SArr)(base);
    SArr As_l = (SArr)(base + ARRW);
    SArr Bs_h = (SArr)(base + 2 * ARRW);
    SArr Bs_l = (SArr)(base + 3 * ARRW);
    float av[16], bv[16];
#pragma unroll
    for (int q = 0; q < 4; q++) {
        float4 v = make_float4(0.f, 0.f, 0.f, 0.f);
        if (mok) v = *(const float4*)(arow + k0 + ak2 * 2 + q * 4);
        av[q * 4 + 0] = v.x; av[q * 4 + 1] = v.y;
        av[q * 4 + 2] = v.z; av[q * 4 + 3] = v.w;
        float4 w = make_float4(0.f, 0.f, 0.f, 0.f);
        if (nok) w = *(const float4*)(brow + k0 + ak2 * 2 + q * 4);
        bv[q * 4 + 0] = w.x; bv[q * 4 + 1] = w.y;
        bv[q * 4 + 2] = w.z; bv[q * 4 + 3] = w.w;
    }
#pragma unroll
    for (int j = 0; j < 8; j++) {
        unsigned hh, ll;
        splitb(av[2 * j], av[2 * j + 1], hh, ll);
        As_h[ak2 + j][ar] = hh;
        As_l[ak2 + j][ar] = ll;
        splitb(bv[2 * j], bv[2 * j + 1], hh, ll);
        Bs_h[ak2 + j][ar] = hh;
        Bs_l[ak2 + j][ar] = ll;
    }
}

// EPI: 0 = store, 1 = gelu-store, 2 = add-to-C (residual)
template<int EPI>
__global__ void __launch_bounds__(256, 2)
k_mma_nn(const float* __restrict__ A, long long lda, long long sAb, long long sAh,
         const float* __restrict__ Bw, long long ldb, long long sBb, long long sBh,
         const float* __restrict__ bias,
         float* __restrict__ C, long long ldc, long long sCb, long long sCh,
         const float* __restrict__ sm_, const float* __restrict__ si_,
         int zdiv, int m_base, int Kfix, float scale) {
    int z = blockIdx.z, b = z / zdiv, h = z - b * zdiv;
    int M = m_base + g_np[b];
    int m0 = blockIdx.y * 128;
    if (m0 >= M) return;
    int K = (Kfix > 0) ? Kfix : M;
    int n0 = blockIdx.x * 128;
    A  += (long long)b * sAb + (long long)h * sAh;
    Bw += (long long)b * sBb + (long long)h * sBh;
    C  += (long long)b * sCb + (long long)h * sCh;
    extern __shared__ unsigned smem_u[];
    int tid = threadIdx.x, lane = tid & 31, warp = tid >> 5;
    int g = lane >> 2, t = lane & 3;
    int wm = warp & 1, wn = warp >> 1;
    float acc[4][4][4] = {};

    // fused-softmax row stats for the A operand (row fixed per thread)
    int ex = (sm_ != nullptr);
    float rm = 0.0f, ri = 1.0f;
    if (ex) {
        int gm = m0 + (tid >> 1);
        if (gm < M) {
            long long ridx = (long long)z * NMAX + gm;
            rm = sm_[ridx];
            ri = si_[ridx];
        }
    }

    stage_nn(smem_u, A, lda, M, K, m0, Bw, ldb, n0, 0, tid, ex, rm, ri);
    __syncthreads();
    int buf = 0;
    for (int k0 = 0; k0 < K; k0 += KT) {
        unsigned* cur = smem_u + buf * STGW;
        unsigned* nxt = smem_u + (buf ^ 1) * STGW;
        int kn = k0 + KT;
        if (kn < K) stage_nn(nxt, A, lda, M, K, m0, Bw, ldb, n0, kn, tid, ex, rm, ri);
        {
            SArr As_h = (SArr)(cur);
            SArr As_l = (SArr)(cur + ARRW);
            SArr Bs_h = (SArr)(cur + 2 * ARRW);
            SArr Bs_l = (SArr)(cur + 3 * ARRW);
            MMA_BODY(As_h, As_l, Bs_h, Bs_l)
        }
        __syncthreads();
        buf ^= 1;
    }
    // ---- epilogue ----
#pragma unroll
    for (int ma = 0; ma < 4; ma++) {
        int r0 = m0 + wm * 64 + ma * 16 + g;
#pragma unroll
        for (int half = 0; half < 2; half++) {
            int gm = r0 + half * 8;
            if (gm >= M) continue;
            float* crow = C + (long long)gm * ldc;
#pragma unroll
            for (int na = 0; na < 4; na++) {
                int gn = n0 + wn * 32 + na * 8 + t * 2;
                float v0 = acc[ma][na][half * 2 + 0] * scale + (bias ? bias[gn] : 0.0f);
                float v1 = acc[ma][na][half * 2 + 1] * scale + (bias ? bias[gn + 1] : 0.0f);
                if (EPI == 1) { v0 = gelu_f(v0); v1 = gelu_f(v1); }
                if (EPI == 2) { crow[gn] += v0; crow[gn + 1] += v1; }
                else          { crow[gn] = v0;  crow[gn + 1] = v1; }
            }
        }
    }
}

// =============================================================================
// BF16 split MMA GEMM (NT): attention scores C[nq][nk] = scale * Q @ K^T
// K = HD = 256 (multiple of KT). Double-buffered, 1 sync/iter.
// =============================================================================
__global__ void __launch_bounds__(256, 2)
k_mma_nt(const float* __restrict__ A, long long lda, long long sAb, long long sAh,
         const float* __restrict__ Bk, long long ldb, long long sBb, long long sBh,
         float* __restrict__ C, long long ldc, long long sCb, long long sCh,
         float scale) {
    int z = blockIdx.z, b = z >> 2, h = z & 3;
    int M = 1025 + g_np[b];
    int m0 = blockIdx.y * 128;
    int n0 = blockIdx.x * 128;
    if (m0 >= M || n0 >= M) return;
    A  += (long long)b * sAb + (long long)h * sAh;
    Bk += (long long)b * sBb + (long long)h * sBh;
    C  += (long long)b * sCb + (long long)h * sCh;
    extern __shared__ unsigned smem_u[];
    int tid = threadIdx.x, lane = tid & 31, warp = tid >> 5;
    int g = lane >> 2, t = lane & 3;
    int wm = warp & 1, wn = warp >> 1;
    float acc[4][4][4] = {};
    int ar = tid >> 1, ak2 = (tid & 1) * 8;
    int gm = m0 + ar, gn = n0 + ar;
    bool mok = gm < M, nok = gn < M;
    const float* arow = A + (long long)gm * lda;
    const float* brow = Bk + (long long)gn * ldb;

    stage_nt(smem_u, arow, mok, brow, nok, 0, ar, ak2);
    __syncthreads();
    int buf = 0;
    for (int k0 = 0; k0 < HD; k0 += KT) {
        unsigned* cur = smem_u + buf * STGW;
        unsigned* nxt = smem_u + (buf ^ 1) * STGW;
        int kn = k0 + KT;
        if (kn < HD) stage_nt(nxt, arow, mok, brow, nok, kn, ar, ak2);
        {
            SArr As_h = (SArr)(cur);
            SArr As_l = (SArr)(cur + ARRW);
            SArr Bs_h = (SArr)(cur + 2 * ARRW);
            SArr Bs_l = (SArr)(cur + 3 * ARRW);
            MMA_BODY(As_h, As_l, Bs_h, Bs_l)
        }
        __syncthreads();
        buf ^= 1;
    }
#pragma unroll
    for (int ma = 0; ma < 4; ma++) {
        int r0 = m0 + wm * 64 + ma * 16 + g;
#pragma unroll
        for (int half = 0; half < 2; half++) {
            int gmr = r0 + half * 8;
            if (gmr >= M) continue;
            float* crow = C + (long long)gmr * ldc;
#pragma unroll
            for (int na = 0; na < 4; na++) {
                int gnc = n0 + wn * 32 + na * 8 + t * 2;
                if (gnc >= M) continue;
                crow[gnc]     = acc[ma][na][half * 2 + 0] * scale;
                crow[gnc + 1] = acc[ma][na][half * 2 + 1] * scale;
            }
        }
    }
}

// ---------------- softmax stats only: row max + 1/sum (single read pass) ----
__global__ void k_sm_stats() {
    int n = blockIdx.x, h = blockIdx.y, b = blockIdx.z;
    int L = 1025 + g_np[b];
    if (n >= L) return;
    const float* row = &g_s[((size_t)(b * NHEAD + h) * NMAX + n) * SLD];
    int tid = threadIdx.x;
    __shared__ float smx[256], ssm[256];
    float mx = -1e30f, sm = 0.0f;
    for (int m = tid; m < L; m += 256) {
        float v = row[m];
        float nm = fmaxf(mx, v);
        sm = sm * __expf(mx - nm) + __expf(v - nm);
        mx = nm;
    }
    smx[tid] = mx; ssm[tid] = sm;
    __syncthreads();
    for (int o = 128; o > 0; o >>= 1) {
        if (tid < o) {
            float m2 = smx[tid + o], s2 = ssm[tid + o];
            float m1 = smx[tid],     s1 = ssm[tid];
            float nm = fmaxf(m1, m2);
            ssm[tid] = s1 * __expf(m1 - nm) + s2 * __expf(m2 - nm);
            smx[tid] = nm;
        }
        __syncthreads();
    }
    if (tid == 0) {
        size_t idx = (size_t)(b * NHEAD + h) * NMAX + n;
        g_mx[idx]  = smx[0];
        g_inv[idx] = 1.0f / ssm[0];
    }
}

// ---------------- final output ----------------
__global__ void k_out(const float* __restrict__ img, float* __restrict__ out) {
    int t = blockIdx.x, b = blockIdx.y, tid = threadIdx.x;
    bool use = (g_np[b] > 0);
    const float* x = &g_x[((size_t)b * NMAX + t) * DIM];
    const float* im = &img[((size_t)b * 1024 + t) * DIM];
    float* o = &out[((size_t)b * 1024 + t) * DIM];
    for (int c = tid; c < DIM; c += 256) o[c] = use ? x[c] : im[c];
}

// ---------------- launcher ----------------
extern "C" void kernel_launch(void* const* d_in, const int* in_sizes, int n_in,
                              void* d_out, int out_size) {
    const float* img   = (const float*)d_in[0];
    const float* depth = (const float*)d_in[1];
    const int*   mask  = (const int*)d_in[2];
    const float* gauss = (const float*)d_in[5];
    const float* w1    = (const float*)d_in[6];
    const float* b1    = (const float*)d_in[7];
    const float* w2    = (const float*)d_in[8];
    const float* b2    = (const float*)d_in[9];
    const float* sep   = (const float*)d_in[10];
    const float* ln1w  = (const float*)d_in[11];
    const float* ln1b  = (const float*)d_in[12];
    const float* qkvw  = (const float*)d_in[13];
    const float* qkvb  = (const float*)d_in[14];
    const float* projw = (const float*)d_in[15];
    const float* projb = (const float*)d_in[16];
    const float* ln2w  = (const float*)d_in[17];
    const float* ln2b  = (const float*)d_in[18];
    const float* m1w   = (const float*)d_in[19];
    const float* m1b   = (const float*)d_in[20];
    const float* m2w   = (const float*)d_in[21];
    const float* m2b   = (const float*)d_in[22];
    float* out = (float*)d_out;

    float *p_ph, *p_prompt, *p_x, *p_xn, *p_qkv, *p_ao, *p_hb, *p_s, *p_mx, *p_inv;
    cudaGetSymbolAddress((void**)&p_ph, g_ph);
    cudaGetSymbolAddress((void**)&p_prompt, g_prompt);
    cudaGetSymbolAddress((void**)&p_x, g_x);
    cudaGetSymbolAddress((void**)&p_xn, g_xn);
    cudaGetSymbolAddress((void**)&p_qkv, g_qkv);
    cudaGetSymbolAddress((void**)&p_ao, g_ao);
    cudaGetSymbolAddress((void**)&p_hb, g_hb);
    cudaGetSymbolAddress((void**)&p_s, g_s);
    cudaGetSymbolAddress((void**)&p_mx, g_mx);
    cudaGetSymbolAddress((void**)&p_inv, g_inv);

    cudaFuncSetAttribute(k_mma_nn<0>, cudaFuncAttributeMaxDynamicSharedMemorySize, SMEM_BYTES);
    cudaFuncSetAttribute(k_mma_nn<1>, cudaFuncAttributeMaxDynamicSharedMemorySize, SMEM_BYTES);
    cudaFuncSetAttribute(k_mma_nn<2>, cudaFuncAttributeMaxDynamicSharedMemorySize, SMEM_BYTES);
    cudaFuncSetAttribute(k_mma_nt,    cudaFuncAttributeMaxDynamicSharedMemorySize, SMEM_BYTES);

    k_scan<<<BATCH, 256>>>(mask);
    k_qpe<<<1024, 512>>>(gauss);
    k_prompt_init<<<dim3(NPM, BATCH), 256>>>(depth, gauss, w1, b1);
    // prompt = ph @ w2 + b2, added onto PE already stored in g_prompt
    k_mma_nn<2><<<dim3(8, 18, BATCH), 256, SMEM_BYTES>>>(
        p_ph, 512, (long long)NPM * 512, 0,
        w2, 1024, 0, 0, b2,
        p_prompt, 1024, (long long)NPM * 1024, 0,
        nullptr, nullptr,
        1, 0, 512, 1.0f);
    k_build<<<dim3(NMAX, BATCH), 256>>>(img, sep);

    for (int i = 0; i < 2; i++) {
        if (i) k_set_sep<<<dim3(1, BATCH), 256>>>(sep + (size_t)i * DIM);
        // ln1
        k_ln<<<dim3(NMAX, BATCH), 256>>>(p_x, p_xn, ln1w + i * DIM, ln1b + i * DIM);
        // qkv
        k_mma_nn<0><<<dim3(24, 27, BATCH), 256, SMEM_BYTES>>>(
            p_xn, DIM, (long long)NMAX * DIM, 0,
            qkvw + (size_t)i * DIM * 3 * DIM, 3 * DIM, 0, 0, qkvb + (size_t)i * 3 * DIM,
            p_qkv, 3 * DIM, (long long)NMAX * 3 * DIM, 0,
            nullptr, nullptr,
            1, 1025, DIM, 1.0f);
        // scores = (q @ k^T) / 16
        k_mma_nt<<<dim3(27, 27, BATCH * NHEAD), 256, SMEM_BYTES>>>(
            p_qkv, 3 * DIM, (long long)NMAX * 3 * DIM, HD,
            p_qkv + DIM, 3 * DIM, (long long)NMAX * 3 * DIM, HD,
            p_s, SLD, (long long)NHEAD * NMAX * SLD, (long long)NMAX * SLD,
            0.0625f);
        // softmax stats (row max + 1/sum) — normalization fused into AV below
        k_sm_stats<<<dim3(NMAX, NHEAD, BATCH), 256>>>();
        // attn out = softmax(S) @ v  (exp applied in A staging)
        k_mma_nn<0><<<dim3(2, 27, BATCH * NHEAD), 256, SMEM_BYTES>>>(
            p_s, SLD, (long long)NHEAD * NMAX * SLD, (long long)NMAX * SLD,
            p_qkv + 2 * DIM, 3 * DIM, (long long)NMAX * 3 * DIM, HD, nullptr,
            p_ao, DIM, (long long)NMAX * DIM, HD,
            p_mx, p_inv,
            NHEAD, 1025, -1, 1.0f);
        // proj + residual
        k_mma_nn<2><<<dim3(8, 27, BATCH), 256, SMEM_BYTES>>>(
            p_ao, DIM, (long long)NMAX * DIM, 0,
            projw + (size_t)i * DIM * DIM, DIM, 0, 0, projb + (size_t)i * DIM,
            p_x, DIM, (long long)NMAX * DIM, 0,
            nullptr, nullptr,
            1, 1025, DIM, 1.0f);
        // ln2
        k_ln<<<dim3(NMAX, BATCH), 256>>>(p_x, p_xn, ln2w + i * DIM, ln2b + i * DIM);
        // mlp1 (gelu)
        k_mma_nn<1><<<dim3(32, 27, BATCH), 256, SMEM_BYTES>>>(
            p_xn, DIM, (long long)NMAX * DIM, 0,
            m1w + (size_t)i * DIM * FF, FF, 0, 0, m1b + (size_t)i * FF,
            p_hb, FF, (long long)NMAX * FF, 0,
            nullptr, nullptr,
            1, 1025, DIM, 1.0f);
        // mlp2 + residual
        k_mma_nn<2><<<dim3(8, 27, BATCH), 256, SMEM_BYTES>>>(
            p_hb, FF, (long long)NMAX * FF, 0,
            m2w + (size_t)i * FF * DIM, DIM, 0, 0, m2b + (size_t)i * DIM,
            p_x, DIM, (long long)NMAX * DIM, 0,
            nullptr, nullptr,
            1, 1025, FF, 1.0f);
    }
    k_out<<<dim3(1024, BATCH), 256>>>(img, out);
}